// round 3
// baseline (speedup 1.0000x reference)
#include <cuda_runtime.h>
#include <cuda_bf16.h>
#include <math.h>

// Problem shape (fixed by dataset): T=512, N=512, C=80, S=128
#define TT 512
#define CC 80
#define SS 128
#define LL 257            // 2*S + 1
#define LL2 (LL + 2)      // 2-cell NEG pad at the front removes s<1/s<2 predicates
#define NEGV (-1e30f)
#define NTHREADS 288      // 9 warps; threads [257,288) idle in compute, join syncs
#define LOG2E 1.4426950408889634f
#define LN2   0.6931471805599453f

__device__ __forceinline__ float ex2f(float x) {
    float r; asm("ex2.approx.ftz.f32 %0, %1;" : "=f"(r) : "f"(x)); return r;
}
__device__ __forceinline__ float lg2f(float x) {
    float r; asm("lg2.approx.f32 %0, %1;" : "=f"(r) : "f"(x)); return r;
}

// One block = TWO sequences (2 independent LSE chains per thread for ILP).
// Alpha is kept in log2 domain; emissions scaled by log2(e) at load time.
__global__ __launch_bounds__(NTHREADS)
void ctc_loss_kernel(const float* __restrict__ log_probs,     // (T, N, C)
                     const int*   __restrict__ targets,       // (N, S)
                     const int*   __restrict__ input_lengths, // (N,)
                     const int*   __restrict__ target_lengths,// (N,)
                     float*       __restrict__ out,           // (N,)
                     int N)
{
    __shared__ float shA[2][2][LL2];   // [seq][buf][cell+2]

    const int tid = threadIdx.x;
    const int s   = tid;
    const int b   = blockIdx.x;
    const int n0  = 2 * b;
    const int n1  = (2 * b + 1 < N) ? 2 * b + 1 : 2 * b;   // dup-safe for odd N

    const int len0 = input_lengths[n0];
    const int len1 = input_lengths[n1];
    const int tmax = max(len0, len1);

    // Time-invariant per-cell state (registers): label class + skip permission
    int  myc0 = 0, myc1 = 0;
    bool skip0 = false, skip1 = false;
    if (s < LL && (s & 1)) {
        int j = s >> 1;
        myc0 = targets[n0 * SS + j];
        myc1 = targets[n1 * SS + j];
        if (s >= 2) {
            skip0 = (myc0 != targets[n0 * SS + j - 1]);
            skip1 = (myc1 != targets[n1 * SS + j - 1]);
        }
    }

    const size_t tstride = (size_t)N * CC;
    const float* p0 = log_probs + (size_t)n0 * CC + myc0;  // emission column for this cell
    const float* p1 = log_probs + (size_t)n1 * CC + myc1;

    // ---- prologue ----
    if (tid < 2) {   // front pads stay NEG forever
        shA[0][0][tid] = NEGV; shA[0][1][tid] = NEGV;
        shA[1][0][tid] = NEGV; shA[1][1][tid] = NEGV;
    }

    float ec0 = 0.f, ec1 = 0.f;   // emission (log2 units) for current step t
    if (s < LL) {
        // alpha(t=0): only cells 0,1 reachable
        shA[0][0][s + 2] = (s <= 1) ? __ldg(p0) * LOG2E : NEGV;
        shA[1][0][s + 2] = (s <= 1) ? __ldg(p1) * LOG2E : NEGV;
        // emission for t=1 (row 1 always exists: T=512)
        ec0 = __ldg(p0 + tstride) * LOG2E;
        ec1 = __ldg(p1 + tstride) * LOG2E;
    }
    __syncthreads();

    // ---- main DP: iterate only to this block's max length ----
    int cur = 0;
    for (int t = 1; t < tmax; ++t) {
        // register prefetch of next step's emission (clamped row; always in-bounds)
        float en0, en1;
        if (s < LL) {
            const int    tn  = (t + 1 < tmax) ? t + 1 : t;
            const size_t off = (size_t)tn * tstride;
            en0 = __ldg(p0 + off);
            en1 = __ldg(p1 + off);
        }

        float nv0, nv1;
        if (s < LL) {
            // seq 0
            float a0 = shA[0][cur][s + 2];
            float a1 = shA[0][cur][s + 1];
            float a2 = skip0 ? shA[0][cur][s] : NEGV;
            float m  = fmaxf(a0, fmaxf(a1, a2));
            float sum = ex2f(a0 - m) + ex2f(a1 - m) + ex2f(a2 - m);
            nv0 = m + lg2f(sum) + ec0;
            nv0 = (t < len0) ? nv0 : a0;          // freeze finished sequence
            // seq 1 (independent chain — overlaps with seq 0)
            float b0 = shA[1][cur][s + 2];
            float b1 = shA[1][cur][s + 1];
            float b2 = skip1 ? shA[1][cur][s] : NEGV;
            float mb = fmaxf(b0, fmaxf(b1, b2));
            float sb = ex2f(b0 - mb) + ex2f(b1 - mb) + ex2f(b2 - mb);
            nv1 = mb + lg2f(sb) + ec1;
            nv1 = (t < len1) ? nv1 : b0;

            shA[0][cur ^ 1][s + 2] = nv0;
            shA[1][cur ^ 1][s + 2] = nv1;
            ec0 = en0 * LOG2E;
            ec1 = en1 * LOG2E;
        }
        __syncthreads();
        cur ^= 1;
    }

    // ---- epilogue: combine last blank (2*tl) and last label (2*tl-1) ----
    if (tid < 2) {
        const int nn  = 2 * b + tid;
        if (nn < N) {
            const int tl = target_lengths[nn];
            const int i1 = 2 * tl + 2;            // +2 for pad offset
            float v1 = shA[tid][cur][i1];
            float v2 = shA[tid][cur][i1 - 1];
            float m  = fmaxf(v1, v2);
            float loss = -(m + lg2f(ex2f(v1 - m) + ex2f(v2 - m))) * LN2;
            if (!isfinite(loss) || loss >= 1e10f) loss = 0.0f;
            out[nn] = loss;
        }
    }
}

extern "C" void kernel_launch(void* const* d_in, const int* in_sizes, int n_in,
                              void* d_out, int out_size)
{
    const float* log_probs      = (const float*)d_in[0];
    const int*   targets        = (const int*)  d_in[1];
    const int*   input_lengths  = (const int*)  d_in[2];
    const int*   target_lengths = (const int*)  d_in[3];
    float*       out            = (float*)d_out;

    const int N = in_sizes[2];   // batch from input_lengths element count
    const int blocks = (N + 1) / 2;

    ctc_loss_kernel<<<blocks, NTHREADS>>>(log_probs, targets, input_lengths,
                                          target_lengths, out, N);
}